// round 11
// baseline (speedup 1.0000x reference)
#include <cuda_runtime.h>
#include <cuda_bf16.h>
#include <cstdint>
#include <math.h>

// Problem constants
#define Bdim 2
#define Nseq 2048
#define Dmod 1024
#define Hn   16
#define HD   64

// ---------------------------------------------------------------------------
// Scratch (alloc-free rule: __device__ globals)
// ---------------------------------------------------------------------------
#define QKV_ELEMS ((size_t)Bdim * Hn * Nseq * HD)
__device__ __nv_bfloat16 g_Qh[QKV_ELEMS], g_Ql[QKV_ELEMS];   // [b][h][n][d]
__device__ __nv_bfloat16 g_Kh[QKV_ELEMS], g_Kl[QKV_ELEMS];
__device__ __nv_bfloat16 g_Vh[QKV_ELEMS], g_Vl[QKV_ELEMS];
__device__ __nv_bfloat16 g_Vth[QKV_ELEMS], g_Vtl[QKV_ELEMS]; // [b][h][d][n]

__device__ __nv_bfloat16 g_xh[(size_t)4096 * 1024];
__device__ __nv_bfloat16 g_xl[(size_t)4096 * 1024];
__device__ __nv_bfloat16 g_oh[(size_t)4096 * 1024];          // attn out [b][n][1024]
__device__ __nv_bfloat16 g_ol[(size_t)4096 * 1024];
__device__ __nv_bfloat16 g_wth[4][(size_t)1024 * 1024];      // W^T [n][k]
__device__ __nv_bfloat16 g_wtl[4][(size_t)1024 * 1024];

// ---------------------------------------------------------------------------
// PTX helpers
// ---------------------------------------------------------------------------
__device__ __forceinline__ void mma_bf16(float (&d)[4],
                                         const uint32_t (&a)[4],
                                         const uint32_t (&b)[2])
{
    asm volatile(
        "mma.sync.aligned.m16n8k16.row.col.f32.bf16.bf16.f32 "
        "{%0,%1,%2,%3}, {%4,%5,%6,%7}, {%8,%9}, {%0,%1,%2,%3};"
        : "+f"(d[0]), "+f"(d[1]), "+f"(d[2]), "+f"(d[3])
        : "r"(a[0]), "r"(a[1]), "r"(a[2]), "r"(a[3]),
          "r"(b[0]), "r"(b[1]));
}

__device__ __forceinline__ void ldsm_x4(uint32_t (&r)[4], uint32_t addr)
{
    asm volatile("ldmatrix.sync.aligned.m8n8.x4.shared.b16 {%0,%1,%2,%3}, [%4];"
                 : "=r"(r[0]), "=r"(r[1]), "=r"(r[2]), "=r"(r[3]) : "r"(addr));
}

__device__ __forceinline__ uint32_t smem_to_u32(const void* p) {
    uint32_t a;
    asm("{ .reg .u64 t; cvta.to.shared.u64 t, %1; cvt.u32.u64 %0, t; }"
        : "=r"(a) : "l"(p));
    return a;
}

#define CP_ASYNC16(saddr, gptr) \
    asm volatile("cp.async.cg.shared.global [%0], [%1], 16;" \
                 :: "r"(saddr), "l"(gptr) : "memory")
#define CP_COMMIT() asm volatile("cp.async.commit_group;" ::: "memory")
#define CP_WAIT1()  asm volatile("cp.async.wait_group 1;" ::: "memory")
#define CP_WAIT0()  asm volatile("cp.async.wait_group 0;" ::: "memory")

__device__ __forceinline__ uint32_t pack2(float a, float b)
{
    return (uint32_t)__bfloat16_as_ushort(__float2bfloat16_rn(a)) |
           ((uint32_t)__bfloat16_as_ushort(__float2bfloat16_rn(b)) << 16);
}

__device__ __forceinline__ void split1(float v, float& hf, float& lf)
{
    __nv_bfloat16 h = __float2bfloat16_rn(v);
    hf = __bfloat162float(h);
    lf = v - hf;
}

// ---------------------------------------------------------------------------
// Conversions
// ---------------------------------------------------------------------------
__device__ __forceinline__ void split4(float4 v, ushort4& H, ushort4& L)
{
    __nv_bfloat16 h0 = __float2bfloat16_rn(v.x);
    __nv_bfloat16 h1 = __float2bfloat16_rn(v.y);
    __nv_bfloat16 h2 = __float2bfloat16_rn(v.z);
    __nv_bfloat16 h3 = __float2bfloat16_rn(v.w);
    H = {__bfloat16_as_ushort(h0), __bfloat16_as_ushort(h1),
         __bfloat16_as_ushort(h2), __bfloat16_as_ushort(h3)};
    L = {__bfloat16_as_ushort(__float2bfloat16_rn(v.x - __bfloat162float(h0))),
         __bfloat16_as_ushort(__float2bfloat16_rn(v.y - __bfloat162float(h1))),
         __bfloat16_as_ushort(__float2bfloat16_rn(v.z - __bfloat162float(h2))),
         __bfloat16_as_ushort(__float2bfloat16_rn(v.w - __bfloat162float(h3)))};
}

__global__ void conv_split_x(const float4* __restrict__ src)
{
    int i = blockIdx.x * 256 + threadIdx.x;
    ushort4 H, L;
    split4(src[i], H, L);
    ((ushort4*)g_xh)[i] = H;
    ((ushort4*)g_xl)[i] = L;
}

__global__ void conv_w(const float* __restrict__ Wq, const float* __restrict__ Wk,
                       const float* __restrict__ Wv, const float* __restrict__ Wo)
{
    __shared__ float t[32][33];
    int z = blockIdx.z;
    const float* W = (z == 0) ? Wq : (z == 1) ? Wk : (z == 2) ? Wv : Wo;
    int n0 = blockIdx.x * 32, k0 = blockIdx.y * 32;
    int tx = threadIdx.x, ty = threadIdx.y;
#pragma unroll
    for (int j = 0; j < 32; j += 8)
        t[ty + j][tx] = W[(size_t)(k0 + ty + j) * 1024 + n0 + tx];
    __syncthreads();
#pragma unroll
    for (int j = 0; j < 32; j += 8) {
        float v = t[tx][ty + j];
        __nv_bfloat16 h = __float2bfloat16_rn(v);
        __nv_bfloat16 l = __float2bfloat16_rn(v - __bfloat162float(h));
        size_t idx = (size_t)(n0 + ty + j) * 1024 + k0 + tx;
        g_wth[z][idx] = h;
        g_wtl[z][idx] = l;
    }
}

// V [bh][n][d] -> Vt [bh][d][n], hi+lo
__global__ void transpose_v()
{
    __shared__ __nv_bfloat16 th[32][33], tl[32][33];
    int bh = blockIdx.z;
    int n0 = blockIdx.x * 32, d0 = blockIdx.y * 32;
    int tx = threadIdx.x, ty = threadIdx.y;
#pragma unroll
    for (int j = 0; j < 32; j += 8) {
        size_t src = ((size_t)bh * 2048 + n0 + ty + j) * 64 + d0 + tx;
        th[ty + j][tx] = g_Vh[src];
        tl[ty + j][tx] = g_Vl[src];
    }
    __syncthreads();
#pragma unroll
    for (int j = 0; j < 32; j += 8) {
        size_t dst = ((size_t)bh * 64 + d0 + ty + j) * 2048 + n0 + tx;
        g_Vth[dst] = th[tx][ty + j];
        g_Vtl[dst] = tl[tx][ty + j];
    }
}

// ---------------------------------------------------------------------------
// HMMA bf16x3 GEMM with ldmatrix fragments + cp.async double buffering (R7).
// C[4096,1024] = A @ B^T + bias (B stored [n][k]).
// ---------------------------------------------------------------------------
#define TSTRIDE 20
#define GT 10240
#define GBUF (4 * GT)
#define GEMM_SMEM (2 * GBUF)

template <bool HEAD>
__device__ __forceinline__ void mma_gemm_body(const __nv_bfloat16* __restrict__ Ahi,
                                              const __nv_bfloat16* __restrict__ Alo,
                                              const __nv_bfloat16* __restrict__ Bhi,
                                              const __nv_bfloat16* __restrict__ Blo,
                                              const float* __restrict__ bias,
                                              float* __restrict__ out,
                                              __nv_bfloat16* __restrict__ outH,
                                              __nv_bfloat16* __restrict__ outL)
{
    extern __shared__ char gsm[];
    const uint32_t gb = smem_to_u32(gsm);

    const int tid = threadIdx.x;
    const int wid = tid >> 5;
    const int lid = tid & 31;
    const int wm  = wid & 3;
    const int wn  = wid >> 2;
    const int gq  = lid >> 2;
    const int tq  = lid & 3;
    const int lt  = lid >> 3;
    const int lr  = lid & 7;
    const int m0 = blockIdx.y * 128;
    const int n0 = blockIdx.x * 128;

    const int u0row = (tid * 2) >> 2;
    const int u0c4  = (tid * 2) & 3;
    const int u1row = (tid * 2 + 1) >> 2;
    const int u1c4  = (tid * 2 + 1) & 3;

#define G_LOAD(kt, bi) do { \
        uint32_t buf = gb + (bi) * GBUF; \
        { \
            uint32_t so = (uint32_t)(u0row * TSTRIDE + u0c4 * 4) * 4; \
            const char* pa = (const char*)(Ahi + (size_t)(m0 + u0row) * 1024 + (kt)); \
            const char* pal = (const char*)(Alo + (size_t)(m0 + u0row) * 1024 + (kt)); \
            const char* pb = (const char*)(Bhi + (size_t)(n0 + u0row) * 1024 + (kt)); \
            const char* pbl = (const char*)(Blo + (size_t)(n0 + u0row) * 1024 + (kt)); \
            CP_ASYNC16(buf + so,          pa  + u0c4 * 16); \
            CP_ASYNC16(buf + GT + so,     pal + u0c4 * 16); \
            CP_ASYNC16(buf + 2 * GT + so, pb  + u0c4 * 16); \
            CP_ASYNC16(buf + 3 * GT + so, pbl + u0c4 * 16); \
        } \
        { \
            uint32_t so = (uint32_t)(u1row * TSTRIDE + u1c4 * 4) * 4; \
            const char* pa = (const char*)(Ahi + (size_t)(m0 + u1row) * 1024 + (kt)); \
            const char* pal = (const char*)(Alo + (size_t)(m0 + u1row) * 1024 + (kt)); \
            const char* pb = (const char*)(Bhi + (size_t)(n0 + u1row) * 1024 + (kt)); \
            const char* pbl = (const char*)(Blo + (size_t)(n0 + u1row) * 1024 + (kt)); \
            CP_ASYNC16(buf + so,          pa  + u1c4 * 16); \
            CP_ASYNC16(buf + GT + so,     pal + u1c4 * 16); \
            CP_ASYNC16(buf + 2 * GT + so, pb  + u1c4 * 16); \
            CP_ASYNC16(buf + 3 * GT + so, pbl + u1c4 * 16); \
        } \
        CP_COMMIT(); \
    } while (0)

    float acc[2][8][4];
#pragma unroll
    for (int mt = 0; mt < 2; mt++)
#pragma unroll
        for (int nt = 0; nt < 8; nt++)
#pragma unroll
            for (int e = 0; e < 4; e++) acc[mt][nt][e] = 0.f;

    G_LOAD(0, 0);
    G_LOAD(32, 1);

    for (int it = 0; it < 32; it++) {
        if (it == 31) { CP_WAIT0(); } else { CP_WAIT1(); }
        __syncthreads();

        const uint32_t buf = gb + (it & 1) * GBUF;
        const uint32_t uAh = buf;
        const uint32_t uAl = buf + GT;
        const uint32_t uBh = buf + 2 * GT;
        const uint32_t uBl = buf + 3 * GT;

#pragma unroll
        for (int ks = 0; ks < 2; ks++) {
            const int c0 = ks * 8;
            uint32_t bh[8][2], bl[8][2];
#pragma unroll
            for (int a = 0; a < 4; a++) {
                int row = wn * 64 + 16 * a + 8 * (lt >> 1) + lr;
                int col = c0 + 4 * (lt & 1);
                uint32_t off = (uint32_t)(row * TSTRIDE + col) * 4;
                uint32_t f[4];
                ldsm_x4(f, uBh + off);
                bh[2 * a][0] = f[0]; bh[2 * a][1] = f[1];
                bh[2 * a + 1][0] = f[2]; bh[2 * a + 1][1] = f[3];
                ldsm_x4(f, uBl + off);
                bl[2 * a][0] = f[0]; bl[2 * a][1] = f[1];
                bl[2 * a + 1][0] = f[2]; bl[2 * a + 1][1] = f[3];
            }
#pragma unroll
            for (int mt = 0; mt < 2; mt++) {
                int row = wm * 32 + 16 * mt + 8 * (lt & 1) + lr;
                int col = c0 + 4 * (lt >> 1);
                uint32_t off = (uint32_t)(row * TSTRIDE + col) * 4;
                uint32_t ah[4], al[4];
                ldsm_x4(ah, uAh + off);
                ldsm_x4(al, uAl + off);
#pragma unroll
                for (int nt = 0; nt < 8; nt++) {
                    mma_bf16(acc[mt][nt], ah, bh[nt]);
                    mma_bf16(acc[mt][nt], ah, bl[nt]);
                    mma_bf16(acc[mt][nt], al, bh[nt]);
                }
            }
        }
        __syncthreads();
        if (it + 2 < 32) G_LOAD((it + 2) * 32, it & 1);
    }

#pragma unroll
    for (int mt = 0; mt < 2; mt++) {
#pragma unroll
        for (int nt = 0; nt < 8; nt++) {
            int R = m0 + wm * 32 + mt * 16 + gq;
            int C = n0 + wn * 64 + nt * 8 + tq * 2;
            float b0 = bias[C], b1 = bias[C + 1];
#pragma unroll
            for (int half = 0; half < 2; half++) {
                int r = R + half * 8;
                float v0 = acc[mt][nt][half * 2 + 0] + b0;
                float v1 = acc[mt][nt][half * 2 + 1] + b1;
                if (HEAD) {
                    int b = r >> 11;
                    int n = r & 2047;
                    int hh = C >> 6;
                    int d = C & 63;
                    float h0, l0, h1, l1;
                    split1(v0, h0, l0);
                    split1(v1, h1, l1);
                    size_t ui = (((size_t)(b * Hn + hh)) * 2048 + n) * 32 + (d >> 1);
                    ((uint32_t*)outH)[ui] = pack2(h0, h1);
                    ((uint32_t*)outL)[ui] = pack2(l0, l1);
                } else {
                    *(float2*)(out + (size_t)r * 1024 + C) = make_float2(v0, v1);
                }
            }
        }
    }
#undef G_LOAD
}

__global__ void __launch_bounds__(256, 2)
mma_qkv(const float* __restrict__ bq, const float* __restrict__ bk,
        const float* __restrict__ bv)
{
    int z = blockIdx.z;
    const float* bias = (z == 0) ? bq : (z == 1) ? bk : bv;
    __nv_bfloat16* oh = (z == 0) ? g_Qh : (z == 1) ? g_Kh : g_Vh;
    __nv_bfloat16* ol = (z == 0) ? g_Ql : (z == 1) ? g_Kl : g_Vl;
    mma_gemm_body<true>(g_xh, g_xl, g_wth[z], g_wtl[z], bias, nullptr, oh, ol);
}

__global__ void __launch_bounds__(256, 2)
mma_out(const float* __restrict__ bo, float* __restrict__ out)
{
    mma_gemm_body<false>(g_oh, g_ol, g_wth[3], g_wtl[3], bo, out, nullptr, nullptr);
}

// ---------------------------------------------------------------------------
// HMMA flash attention v7 (R7 base): ldmatrix + 2-stage cp.async K/V ring,
// Q-hi regs, Q-lo smem. NEW: Gaussian bias folded into S-accumulator init
// (LDG latency hidden behind the S MMA section; exact power-of-2 rescale).
// Smem: 16KB Q-lo + 2 x 32KB = 80KB; 2 CTAs/SM.
// ---------------------------------------------------------------------------
#define QSW(r, w) (((r) * 32) + ((w) ^ (((r) & 7) << 2)))
#define ATT_SMEM (16384 + 2 * 32768)

__global__ void __launch_bounds__(256, 2)
attn_mma(const float* __restrict__ Bg, const float* __restrict__ lam_p)
{
    extern __shared__ char smem[];
    const uint32_t sb = smem_to_u32(smem);

    const int tid = threadIdx.x;
    const int wm  = tid >> 5;
    const int lid = tid & 31;
    const int gq  = lid >> 2;
    const int tq  = lid & 3;
    const int lt  = lid >> 3;
    const int lr  = lid & 7;
    const int qb = blockIdx.x;
    const int h  = blockIdx.y;
    const int b  = blockIdx.z;
    const int bh = b * Hn + h;
    const int q0 = qb * 128;

    const float lam = __ldg(lam_p);
    const float lam8 = lam * 8.0f;      // bias pre-scale (power-of-2 exact)
    const float scale = 0.125f;

    const int r0 = wm * 16 + gq;
    const int qrow = q0 + r0;

    const int ldrow = tid >> 2;
    const int ldq   = tid & 3;
    const uint32_t lw0 = (uint32_t)((4 * ldq) ^ ((ldrow & 7) << 2)) * 4;
    const uint32_t lw1 = (uint32_t)((4 * ldq + 16) ^ ((ldrow & 7) << 2)) * 4;
    const uint32_t lrow128 = (uint32_t)ldrow * 128;

#define LOAD_KB(kb, bi) do { \
        uint32_t bufb = sb + 16384 + (bi) * 32768; \
        const char* pKh = (const char*)(g_Kh + ((size_t)bh * 2048 + (kb) * 64 + ldrow) * 64); \
        const char* pKl = (const char*)(g_Kl + ((size_t)bh * 2048 + (kb) * 64 + ldrow) * 64); \
        const char* pVh = (const char*)(g_Vth + ((size_t)bh * 64 + ldrow) * 2048 + (kb) * 64); \
        const char* pVl = (const char*)(g_Vtl + ((size_t)bh * 64 + ldrow) * 2048 + (kb) * 64); \
        CP_ASYNC16(bufb + lrow128 + lw0, pKh + ldq * 16); \
        CP_ASYNC16(bufb + lrow128 + lw1, pKh + 64 + ldq * 16); \
        CP_ASYNC16(bufb + 8192 + lrow128 + lw0, pKl + ldq * 16); \
        CP_ASYNC16(bufb + 8192 + lrow128 + lw1, pKl + 64 + ldq * 16); \
        CP_ASYNC16(bufb + 16384 + lrow128 + lw0, pVh + ldq * 16); \
        CP_ASYNC16(bufb + 16384 + lrow128 + lw1, pVh + 64 + ldq * 16); \
        CP_ASYNC16(bufb + 24576 + lrow128 + lw0, pVl + ldq * 16); \
        CP_ASYNC16(bufb + 24576 + lrow128 + lw1, pVl + 64 + ldq * 16); \
        CP_COMMIT(); \
    } while (0)

    // Q-lo tile -> smem
    {
        const __nv_bfloat16* Qlg = g_Ql + ((size_t)bh * 2048 + q0) * 64;
#pragma unroll
        for (int i = 0; i < 4; i++) {
            int u = tid + i * 256;
            int row = u >> 3;
            int c4 = u & 7;
            int w = (4 * c4) ^ ((row & 7) << 2);
            *(uint4*)(smem + (row * 32 + w) * 4) = ((const uint4*)(Qlg + (size_t)row * 64))[c4];
        }
    }

    // Q-hi fragments -> registers
    uint32_t qh[4][4];
    {
        const uint32_t* Q32 = (const uint32_t*)g_Qh;
        size_t base0 = ((size_t)bh * 2048 + qrow) * 32;
        size_t base1 = base0 + 8 * 32;
#pragma unroll
        for (int kt = 0; kt < 4; kt++) {
            qh[kt][0] = Q32[base0 + 8 * kt + tq];
            qh[kt][1] = Q32[base1 + 8 * kt + tq];
            qh[kt][2] = Q32[base0 + 8 * kt + 4 + tq];
            qh[kt][3] = Q32[base1 + 8 * kt + 4 + tq];
        }
    }

    LOAD_KB(0, 0);
    LOAD_KB(1, 1);

    float m_i[2] = {-1e30f, -1e30f};
    float l_i[2] = {0.f, 0.f};
    float o[8][4];
#pragma unroll
    for (int nt = 0; nt < 8; nt++)
#pragma unroll
        for (int e = 0; e < 4; e++) o[nt][e] = 0.f;

    const float* Bgb = Bg + (size_t)b * Nseq * Nseq;

    for (int kb = 0; kb < 32; kb++) {
        if (kb == 31) { CP_WAIT0(); } else { CP_WAIT1(); }
        __syncthreads();

        const uint32_t bufb = sb + 16384 + (kb & 1) * 32768;
        const uint32_t uKh = bufb;
        const uint32_t uKl = bufb + 8192;
        const uint32_t uVh = bufb + 16384;
        const uint32_t uVl = bufb + 24576;

        // S accumulator initialized with pre-scaled bias (LDGs issue here,
        // consumed only after the MMA section -> latency hidden)
        float s[8][4];
#pragma unroll
        for (int nt = 0; nt < 8; nt++) {
#pragma unroll
            for (int half = 0; half < 2; half++) {
                int row = qrow + half * 8;
                float2 bg = *(const float2*)(Bgb + (size_t)row * 2048 +
                                             kb * 64 + nt * 8 + tq * 2);
                s[nt][half * 2 + 0] = lam8 * bg.x;
                s[nt][half * 2 + 1] = lam8 * bg.y;
            }
        }

        // S += Q K^T
#pragma unroll
        for (int kt = 0; kt < 4; kt++) {
            uint32_t al[4];
            {
                int row = wm * 16 + 8 * (lt & 1) + lr;
                int wb = 8 * kt + 4 * (lt >> 1);
                ldsm_x4(al, sb + (uint32_t)QSW(row, wb) * 4);
            }
#pragma unroll
            for (int a = 0; a < 4; a++) {
                int row = 16 * a + 8 * (lt >> 1) + lr;
                int wb = 8 * kt + 4 * (lt & 1);
                uint32_t off = (uint32_t)QSW(row, wb) * 4;
                uint32_t kh4[4], kl4[4];
                ldsm_x4(kh4, uKh + off);
                ldsm_x4(kl4, uKl + off);
                uint32_t kh0[2] = {kh4[0], kh4[1]}, kh1[2] = {kh4[2], kh4[3]};
                uint32_t kl0[2] = {kl4[0], kl4[1]}, kl1[2] = {kl4[2], kl4[3]};
                mma_bf16(s[2 * a], qh[kt], kh0);
                mma_bf16(s[2 * a], qh[kt], kl0);
                mma_bf16(s[2 * a], al, kh0);
                mma_bf16(s[2 * a + 1], qh[kt], kh1);
                mma_bf16(s[2 * a + 1], qh[kt], kl1);
                mma_bf16(s[2 * a + 1], al, kh1);
            }
        }

        // final scale: (lam*8*bg + QK) * 0.125 = QK*0.125 + lam*bg (exact)
#pragma unroll
        for (int nt = 0; nt < 8; nt++)
#pragma unroll
            for (int e = 0; e < 4; e++) s[nt][e] *= scale;

        // online softmax
#pragma unroll
        for (int half = 0; half < 2; half++) {
            float mx = -1e30f;
#pragma unroll
            for (int nt = 0; nt < 8; nt++)
                mx = fmaxf(mx, fmaxf(s[nt][half * 2], s[nt][half * 2 + 1]));
            mx = fmaxf(mx, __shfl_xor_sync(0xffffffffu, mx, 1));
            mx = fmaxf(mx, __shfl_xor_sync(0xffffffffu, mx, 2));
            float mn = fmaxf(m_i[half], mx);
            float corr = __expf(m_i[half] - mn);
            m_i[half] = mn;
            float rs = 0.f;
#pragma unroll
            for (int nt = 0; nt < 8; nt++) {
                s[nt][half * 2]     = __expf(s[nt][half * 2] - mn);
                s[nt][half * 2 + 1] = __expf(s[nt][half * 2 + 1] - mn);
                rs += s[nt][half * 2] + s[nt][half * 2 + 1];
            }
            rs += __shfl_xor_sync(0xffffffffu, rs, 1);
            rs += __shfl_xor_sync(0xffffffffu, rs, 2);
            l_i[half] = l_i[half] * corr + rs;
#pragma unroll
            for (int nt = 0; nt < 8; nt++) {
                o[nt][half * 2]     *= corr;
                o[nt][half * 2 + 1] *= corr;
            }
        }

        // O += P V
#pragma unroll
        for (int kt = 0; kt < 4; kt++) {
            float h0, l0, h1, l1, h2, l2, h3, l3;
            uint32_t ph[4], pl[4];
            split1(s[2 * kt][0], h0, l0); split1(s[2 * kt][1], h1, l1);
            split1(s[2 * kt][2], h2, l2); split1(s[2 * kt][3], h3, l3);
            ph[0] = pack2(h0, h1); pl[0] = pack2(l0, l1);
            ph[1] = pack2(h2, h3); pl[1] = pack2(l2, l3);
            split1(s[2 * kt + 1][0], h0, l0); split1(s[2 * kt + 1][1], h1, l1);
            split1(s[2 * kt + 1][2], h2, l2); split1(s[2 * kt + 1][3], h3, l3);
            ph[2] = pack2(h0, h1); pl[2] = pack2(l0, l1);
            ph[3] = pack2(h2, h3); pl[3] = pack2(l2, l3);
#pragma unroll
            for (int a = 0; a < 4; a++) {
                int row = 16 * a + 8 * (lt >> 1) + lr;
                int wb = 8 * kt + 4 * (lt & 1);
                uint32_t off = (uint32_t)QSW(row, wb) * 4;
                uint32_t vh4[4], vl4[4];
                ldsm_x4(vh4, uVh + off);
                ldsm_x4(vl4, uVl + off);
                uint32_t vh0[2] = {vh4[0], vh4[1]}, vh1[2] = {vh4[2], vh4[3]};
                uint32_t vl0[2] = {vl4[0], vl4[1]}, vl1[2] = {vl4[2], vl4[3]};
                mma_bf16(o[2 * a], ph, vh0);
                mma_bf16(o[2 * a], ph, vl0);
                mma_bf16(o[2 * a], pl, vh0);
                mma_bf16(o[2 * a + 1], ph, vh1);
                mma_bf16(o[2 * a + 1], ph, vl1);
                mma_bf16(o[2 * a + 1], pl, vh1);
            }
        }

        __syncthreads();
        if (kb + 2 < 32) LOAD_KB(kb + 2, kb & 1);
    }

    float inv0 = 1.0f / l_i[0];
    float inv1 = 1.0f / l_i[1];
#pragma unroll
    for (int nt = 0; nt < 8; nt++) {
#pragma unroll
        for (int half = 0; half < 2; half++) {
            float inv = half ? inv1 : inv0;
            int row = qrow + half * 8;
            float v0 = o[nt][half * 2 + 0] * inv;
            float v1 = o[nt][half * 2 + 1] * inv;
            float h0, l0, h1, l1;
            split1(v0, h0, l0);
            split1(v1, h1, l1);
            size_t ui = ((size_t)(b * 2048) + row) * 512 + h * 32 + nt * 4 + tq;
            ((uint32_t*)g_oh)[ui] = pack2(h0, h1);
            ((uint32_t*)g_ol)[ui] = pack2(l0, l1);
        }
    }
}

// ---------------------------------------------------------------------------
extern "C" void kernel_launch(void* const* d_in, const int* in_sizes, int n_in,
                              void* d_out, int out_size)
{
    const float* x   = (const float*)d_in[0];
    const float* Bg  = (const float*)d_in[1];
    const float* Wq  = (const float*)d_in[2];
    const float* bq  = (const float*)d_in[3];
    const float* Wk  = (const float*)d_in[4];
    const float* bk  = (const float*)d_in[5];
    const float* Wv  = (const float*)d_in[6];
    const float* bv  = (const float*)d_in[7];
    const float* Wo  = (const float*)d_in[8];
    const float* bo  = (const float*)d_in[9];
    const float* lam = (const float*)d_in[10];
    float* out = (float*)d_out;

    cudaFuncSetAttribute(attn_mma, cudaFuncAttributeMaxDynamicSharedMemorySize, ATT_SMEM);
    cudaFuncSetAttribute(mma_qkv, cudaFuncAttributeMaxDynamicSharedMemorySize, GEMM_SMEM);
    cudaFuncSetAttribute(mma_out, cudaFuncAttributeMaxDynamicSharedMemorySize, GEMM_SMEM);

    conv_split_x<<<4096, 256>>>((const float4*)x);
    conv_w<<<dim3(32, 32, 4), dim3(32, 8)>>>(Wq, Wk, Wv, Wo);

    mma_qkv<<<dim3(8, 32, 3), 256, GEMM_SMEM>>>(bq, bk, bv);
    transpose_v<<<dim3(64, 2, 32), dim3(32, 8)>>>();

    attn_mma<<<dim3(16, 16, 2), 256, ATT_SMEM>>>(Bg, lam);

    mma_out<<<dim3(8, 32, 1), 256, GEMM_SMEM>>>(bo, out);
}

// round 12
// speedup vs baseline: 1.0365x; 1.0365x over previous
#include <cuda_runtime.h>
#include <cuda_bf16.h>
#include <cstdint>
#include <math.h>

// Problem constants
#define Bdim 2
#define Nseq 2048
#define Dmod 1024
#define Hn   16
#define HD   64

// ---------------------------------------------------------------------------
// Scratch (alloc-free rule: __device__ globals)
// ---------------------------------------------------------------------------
#define QKV_ELEMS ((size_t)Bdim * Hn * Nseq * HD)
__device__ __nv_bfloat16 g_Qh[QKV_ELEMS], g_Ql[QKV_ELEMS];   // [b][h][n][d]
__device__ __nv_bfloat16 g_Kh[QKV_ELEMS], g_Kl[QKV_ELEMS];
__device__ __nv_bfloat16 g_Vh[QKV_ELEMS], g_Vl[QKV_ELEMS];
__device__ __nv_bfloat16 g_Vth[QKV_ELEMS], g_Vtl[QKV_ELEMS]; // [b][h][d][n]

__device__ __nv_bfloat16 g_xh[(size_t)4096 * 1024];
__device__ __nv_bfloat16 g_xl[(size_t)4096 * 1024];
__device__ __nv_bfloat16 g_oh[(size_t)4096 * 1024];          // attn out [b][n][1024]
__device__ __nv_bfloat16 g_ol[(size_t)4096 * 1024];
__device__ __nv_bfloat16 g_wth[4][(size_t)1024 * 1024];      // W^T [n][k]
__device__ __nv_bfloat16 g_wtl[4][(size_t)1024 * 1024];

// ---------------------------------------------------------------------------
// PTX helpers
// ---------------------------------------------------------------------------
__device__ __forceinline__ void mma_bf16(float (&d)[4],
                                         const uint32_t (&a)[4],
                                         const uint32_t (&b)[2])
{
    asm volatile(
        "mma.sync.aligned.m16n8k16.row.col.f32.bf16.bf16.f32 "
        "{%0,%1,%2,%3}, {%4,%5,%6,%7}, {%8,%9}, {%0,%1,%2,%3};"
        : "+f"(d[0]), "+f"(d[1]), "+f"(d[2]), "+f"(d[3])
        : "r"(a[0]), "r"(a[1]), "r"(a[2]), "r"(a[3]),
          "r"(b[0]), "r"(b[1]));
}

__device__ __forceinline__ void ldsm_x4(uint32_t (&r)[4], uint32_t addr)
{
    asm volatile("ldmatrix.sync.aligned.m8n8.x4.shared.b16 {%0,%1,%2,%3}, [%4];"
                 : "=r"(r[0]), "=r"(r[1]), "=r"(r[2]), "=r"(r[3]) : "r"(addr));
}

__device__ __forceinline__ uint32_t smem_to_u32(const void* p) {
    uint32_t a;
    asm("{ .reg .u64 t; cvta.to.shared.u64 t, %1; cvt.u32.u64 %0, t; }"
        : "=r"(a) : "l"(p));
    return a;
}

#define CP_ASYNC16(saddr, gptr) \
    asm volatile("cp.async.cg.shared.global [%0], [%1], 16;" \
                 :: "r"(saddr), "l"(gptr) : "memory")
#define CP_COMMIT() asm volatile("cp.async.commit_group;" ::: "memory")
#define CP_WAIT1()  asm volatile("cp.async.wait_group 1;" ::: "memory")
#define CP_WAIT0()  asm volatile("cp.async.wait_group 0;" ::: "memory")

__device__ __forceinline__ uint32_t pack2(float a, float b)
{
    return (uint32_t)__bfloat16_as_ushort(__float2bfloat16_rn(a)) |
           ((uint32_t)__bfloat16_as_ushort(__float2bfloat16_rn(b)) << 16);
}

__device__ __forceinline__ void split1(float v, float& hf, float& lf)
{
    __nv_bfloat16 h = __float2bfloat16_rn(v);
    hf = __bfloat162float(h);
    lf = v - hf;
}

// ---------------------------------------------------------------------------
// Conversions
// ---------------------------------------------------------------------------
__device__ __forceinline__ void split4(float4 v, ushort4& H, ushort4& L)
{
    __nv_bfloat16 h0 = __float2bfloat16_rn(v.x);
    __nv_bfloat16 h1 = __float2bfloat16_rn(v.y);
    __nv_bfloat16 h2 = __float2bfloat16_rn(v.z);
    __nv_bfloat16 h3 = __float2bfloat16_rn(v.w);
    H = {__bfloat16_as_ushort(h0), __bfloat16_as_ushort(h1),
         __bfloat16_as_ushort(h2), __bfloat16_as_ushort(h3)};
    L = {__bfloat16_as_ushort(__float2bfloat16_rn(v.x - __bfloat162float(h0))),
         __bfloat16_as_ushort(__float2bfloat16_rn(v.y - __bfloat162float(h1))),
         __bfloat16_as_ushort(__float2bfloat16_rn(v.z - __bfloat162float(h2))),
         __bfloat16_as_ushort(__float2bfloat16_rn(v.w - __bfloat162float(h3)))};
}

__global__ void conv_split_x(const float4* __restrict__ src)
{
    int i = blockIdx.x * 256 + threadIdx.x;
    ushort4 H, L;
    split4(src[i], H, L);
    ((ushort4*)g_xh)[i] = H;
    ((ushort4*)g_xl)[i] = L;
}

__global__ void conv_w(const float* __restrict__ Wq, const float* __restrict__ Wk,
                       const float* __restrict__ Wv, const float* __restrict__ Wo)
{
    __shared__ float t[32][33];
    int z = blockIdx.z;
    const float* W = (z == 0) ? Wq : (z == 1) ? Wk : (z == 2) ? Wv : Wo;
    int n0 = blockIdx.x * 32, k0 = blockIdx.y * 32;
    int tx = threadIdx.x, ty = threadIdx.y;
#pragma unroll
    for (int j = 0; j < 32; j += 8)
        t[ty + j][tx] = W[(size_t)(k0 + ty + j) * 1024 + n0 + tx];
    __syncthreads();
#pragma unroll
    for (int j = 0; j < 32; j += 8) {
        float v = t[tx][ty + j];
        __nv_bfloat16 h = __float2bfloat16_rn(v);
        __nv_bfloat16 l = __float2bfloat16_rn(v - __bfloat162float(h));
        size_t idx = (size_t)(n0 + ty + j) * 1024 + k0 + tx;
        g_wth[z][idx] = h;
        g_wtl[z][idx] = l;
    }
}

// V [bh][n][d] -> Vt [bh][d][n], hi+lo
__global__ void transpose_v()
{
    __shared__ __nv_bfloat16 th[32][33], tl[32][33];
    int bh = blockIdx.z;
    int n0 = blockIdx.x * 32, d0 = blockIdx.y * 32;
    int tx = threadIdx.x, ty = threadIdx.y;
#pragma unroll
    for (int j = 0; j < 32; j += 8) {
        size_t src = ((size_t)bh * 2048 + n0 + ty + j) * 64 + d0 + tx;
        th[ty + j][tx] = g_Vh[src];
        tl[ty + j][tx] = g_Vl[src];
    }
    __syncthreads();
#pragma unroll
    for (int j = 0; j < 32; j += 8) {
        size_t dst = ((size_t)bh * 64 + d0 + ty + j) * 2048 + n0 + tx;
        g_Vth[dst] = th[tx][ty + j];
        g_Vtl[dst] = tl[tx][ty + j];
    }
}

// ---------------------------------------------------------------------------
// HMMA bf16x3 GEMM with ldmatrix fragments + cp.async double buffering (R7).
// C[4096,1024] = A @ B^T + bias (B stored [n][k]).
// ---------------------------------------------------------------------------
#define TSTRIDE 20
#define GT 10240
#define GBUF (4 * GT)
#define GEMM_SMEM (2 * GBUF)

template <bool HEAD>
__device__ __forceinline__ void mma_gemm_body(const __nv_bfloat16* __restrict__ Ahi,
                                              const __nv_bfloat16* __restrict__ Alo,
                                              const __nv_bfloat16* __restrict__ Bhi,
                                              const __nv_bfloat16* __restrict__ Blo,
                                              const float* __restrict__ bias,
                                              float* __restrict__ out,
                                              __nv_bfloat16* __restrict__ outH,
                                              __nv_bfloat16* __restrict__ outL)
{
    extern __shared__ char gsm[];
    const uint32_t gb = smem_to_u32(gsm);

    const int tid = threadIdx.x;
    const int wid = tid >> 5;
    const int lid = tid & 31;
    const int wm  = wid & 3;
    const int wn  = wid >> 2;
    const int gq  = lid >> 2;
    const int tq  = lid & 3;
    const int lt  = lid >> 3;
    const int lr  = lid & 7;
    const int m0 = blockIdx.y * 128;
    const int n0 = blockIdx.x * 128;

    const int u0row = (tid * 2) >> 2;
    const int u0c4  = (tid * 2) & 3;
    const int u1row = (tid * 2 + 1) >> 2;
    const int u1c4  = (tid * 2 + 1) & 3;

#define G_LOAD(kt, bi) do { \
        uint32_t buf = gb + (bi) * GBUF; \
        { \
            uint32_t so = (uint32_t)(u0row * TSTRIDE + u0c4 * 4) * 4; \
            const char* pa = (const char*)(Ahi + (size_t)(m0 + u0row) * 1024 + (kt)); \
            const char* pal = (const char*)(Alo + (size_t)(m0 + u0row) * 1024 + (kt)); \
            const char* pb = (const char*)(Bhi + (size_t)(n0 + u0row) * 1024 + (kt)); \
            const char* pbl = (const char*)(Blo + (size_t)(n0 + u0row) * 1024 + (kt)); \
            CP_ASYNC16(buf + so,          pa  + u0c4 * 16); \
            CP_ASYNC16(buf + GT + so,     pal + u0c4 * 16); \
            CP_ASYNC16(buf + 2 * GT + so, pb  + u0c4 * 16); \
            CP_ASYNC16(buf + 3 * GT + so, pbl + u0c4 * 16); \
        } \
        { \
            uint32_t so = (uint32_t)(u1row * TSTRIDE + u1c4 * 4) * 4; \
            const char* pa = (const char*)(Ahi + (size_t)(m0 + u1row) * 1024 + (kt)); \
            const char* pal = (const char*)(Alo + (size_t)(m0 + u1row) * 1024 + (kt)); \
            const char* pb = (const char*)(Bhi + (size_t)(n0 + u1row) * 1024 + (kt)); \
            const char* pbl = (const char*)(Blo + (size_t)(n0 + u1row) * 1024 + (kt)); \
            CP_ASYNC16(buf + so,          pa  + u1c4 * 16); \
            CP_ASYNC16(buf + GT + so,     pal + u1c4 * 16); \
            CP_ASYNC16(buf + 2 * GT + so, pb  + u1c4 * 16); \
            CP_ASYNC16(buf + 3 * GT + so, pbl + u1c4 * 16); \
        } \
        CP_COMMIT(); \
    } while (0)

    float acc[2][8][4];
#pragma unroll
    for (int mt = 0; mt < 2; mt++)
#pragma unroll
        for (int nt = 0; nt < 8; nt++)
#pragma unroll
            for (int e = 0; e < 4; e++) acc[mt][nt][e] = 0.f;

    G_LOAD(0, 0);
    G_LOAD(32, 1);

    for (int it = 0; it < 32; it++) {
        if (it == 31) { CP_WAIT0(); } else { CP_WAIT1(); }
        __syncthreads();

        const uint32_t buf = gb + (it & 1) * GBUF;
        const uint32_t uAh = buf;
        const uint32_t uAl = buf + GT;
        const uint32_t uBh = buf + 2 * GT;
        const uint32_t uBl = buf + 3 * GT;

#pragma unroll
        for (int ks = 0; ks < 2; ks++) {
            const int c0 = ks * 8;
            uint32_t bh[8][2], bl[8][2];
#pragma unroll
            for (int a = 0; a < 4; a++) {
                int row = wn * 64 + 16 * a + 8 * (lt >> 1) + lr;
                int col = c0 + 4 * (lt & 1);
                uint32_t off = (uint32_t)(row * TSTRIDE + col) * 4;
                uint32_t f[4];
                ldsm_x4(f, uBh + off);
                bh[2 * a][0] = f[0]; bh[2 * a][1] = f[1];
                bh[2 * a + 1][0] = f[2]; bh[2 * a + 1][1] = f[3];
                ldsm_x4(f, uBl + off);
                bl[2 * a][0] = f[0]; bl[2 * a][1] = f[1];
                bl[2 * a + 1][0] = f[2]; bl[2 * a + 1][1] = f[3];
            }
#pragma unroll
            for (int mt = 0; mt < 2; mt++) {
                int row = wm * 32 + 16 * mt + 8 * (lt & 1) + lr;
                int col = c0 + 4 * (lt >> 1);
                uint32_t off = (uint32_t)(row * TSTRIDE + col) * 4;
                uint32_t ah[4], al[4];
                ldsm_x4(ah, uAh + off);
                ldsm_x4(al, uAl + off);
#pragma unroll
                for (int nt = 0; nt < 8; nt++) {
                    mma_bf16(acc[mt][nt], ah, bh[nt]);
                    mma_bf16(acc[mt][nt], ah, bl[nt]);
                    mma_bf16(acc[mt][nt], al, bh[nt]);
                }
            }
        }
        __syncthreads();
        if (it + 2 < 32) G_LOAD((it + 2) * 32, it & 1);
    }

#pragma unroll
    for (int mt = 0; mt < 2; mt++) {
#pragma unroll
        for (int nt = 0; nt < 8; nt++) {
            int R = m0 + wm * 32 + mt * 16 + gq;
            int C = n0 + wn * 64 + nt * 8 + tq * 2;
            float b0 = bias[C], b1 = bias[C + 1];
#pragma unroll
            for (int half = 0; half < 2; half++) {
                int r = R + half * 8;
                float v0 = acc[mt][nt][half * 2 + 0] + b0;
                float v1 = acc[mt][nt][half * 2 + 1] + b1;
                if (HEAD) {
                    int b = r >> 11;
                    int n = r & 2047;
                    int hh = C >> 6;
                    int d = C & 63;
                    float h0, l0, h1, l1;
                    split1(v0, h0, l0);
                    split1(v1, h1, l1);
                    size_t ui = (((size_t)(b * Hn + hh)) * 2048 + n) * 32 + (d >> 1);
                    ((uint32_t*)outH)[ui] = pack2(h0, h1);
                    ((uint32_t*)outL)[ui] = pack2(l0, l1);
                } else {
                    *(float2*)(out + (size_t)r * 1024 + C) = make_float2(v0, v1);
                }
            }
        }
    }
#undef G_LOAD
}

__global__ void __launch_bounds__(256, 2)
mma_qkv(const float* __restrict__ bq, const float* __restrict__ bk,
        const float* __restrict__ bv)
{
    int z = blockIdx.z;
    const float* bias = (z == 0) ? bq : (z == 1) ? bk : bv;
    __nv_bfloat16* oh = (z == 0) ? g_Qh : (z == 1) ? g_Kh : g_Vh;
    __nv_bfloat16* ol = (z == 0) ? g_Ql : (z == 1) ? g_Kl : g_Vl;
    mma_gemm_body<true>(g_xh, g_xl, g_wth[z], g_wtl[z], bias, nullptr, oh, ol);
}

__global__ void __launch_bounds__(256, 2)
mma_out(const float* __restrict__ bo, float* __restrict__ out)
{
    mma_gemm_body<false>(g_oh, g_ol, g_wth[3], g_wtl[3], bo, out, nullptr, nullptr);
}

// ---------------------------------------------------------------------------
// HMMA flash attention v8 (exact R7 base) with:
//  - base-2 softmax: log2e folded into scale/lam, exp2f (no FMUL per exp)
//  - deferred l-reduction: per-thread partial sums, quad-reduce in epilogue
// Smem: 16KB Q-lo + 2 x 32KB K/V = 80KB; 2 CTAs/SM.
// ---------------------------------------------------------------------------
#define QSW(r, w) (((r) * 32) + ((w) ^ (((r) & 7) << 2)))
#define ATT_SMEM (16384 + 2 * 32768)
#define LOG2E 1.4426950408889634f

__global__ void __launch_bounds__(256, 2)
attn_mma(const float* __restrict__ Bg, const float* __restrict__ lam_p)
{
    extern __shared__ char smem[];
    const uint32_t sb = smem_to_u32(smem);

    const int tid = threadIdx.x;
    const int wm  = tid >> 5;
    const int lid = tid & 31;
    const int gq  = lid >> 2;
    const int tq  = lid & 3;
    const int lt  = lid >> 3;
    const int lr  = lid & 7;
    const int qb = blockIdx.x;
    const int h  = blockIdx.y;
    const int b  = blockIdx.z;
    const int bh = b * Hn + h;
    const int q0 = qb * 128;

    const float lam2   = __ldg(lam_p) * LOG2E;   // lam * log2(e)
    const float scale2 = 0.125f * LOG2E;         // (1/sqrt(64)) * log2(e)

    const int r0 = wm * 16 + gq;
    const int qrow = q0 + r0;

    const int ldrow = tid >> 2;
    const int ldq   = tid & 3;
    const uint32_t lw0 = (uint32_t)((4 * ldq) ^ ((ldrow & 7) << 2)) * 4;
    const uint32_t lw1 = (uint32_t)((4 * ldq + 16) ^ ((ldrow & 7) << 2)) * 4;
    const uint32_t lrow128 = (uint32_t)ldrow * 128;

#define LOAD_KB(kb, bi) do { \
        uint32_t bufb = sb + 16384 + (bi) * 32768; \
        const char* pKh = (const char*)(g_Kh + ((size_t)bh * 2048 + (kb) * 64 + ldrow) * 64); \
        const char* pKl = (const char*)(g_Kl + ((size_t)bh * 2048 + (kb) * 64 + ldrow) * 64); \
        const char* pVh = (const char*)(g_Vth + ((size_t)bh * 64 + ldrow) * 2048 + (kb) * 64); \
        const char* pVl = (const char*)(g_Vtl + ((size_t)bh * 64 + ldrow) * 2048 + (kb) * 64); \
        CP_ASYNC16(bufb + lrow128 + lw0, pKh + ldq * 16); \
        CP_ASYNC16(bufb + lrow128 + lw1, pKh + 64 + ldq * 16); \
        CP_ASYNC16(bufb + 8192 + lrow128 + lw0, pKl + ldq * 16); \
        CP_ASYNC16(bufb + 8192 + lrow128 + lw1, pKl + 64 + ldq * 16); \
        CP_ASYNC16(bufb + 16384 + lrow128 + lw0, pVh + ldq * 16); \
        CP_ASYNC16(bufb + 16384 + lrow128 + lw1, pVh + 64 + ldq * 16); \
        CP_ASYNC16(bufb + 24576 + lrow128 + lw0, pVl + ldq * 16); \
        CP_ASYNC16(bufb + 24576 + lrow128 + lw1, pVl + 64 + ldq * 16); \
        CP_COMMIT(); \
    } while (0)

    // Q-lo tile -> smem
    {
        const __nv_bfloat16* Qlg = g_Ql + ((size_t)bh * 2048 + q0) * 64;
#pragma unroll
        for (int i = 0; i < 4; i++) {
            int u = tid + i * 256;
            int row = u >> 3;
            int c4 = u & 7;
            int w = (4 * c4) ^ ((row & 7) << 2);
            *(uint4*)(smem + (row * 32 + w) * 4) = ((const uint4*)(Qlg + (size_t)row * 64))[c4];
        }
    }

    // Q-hi fragments -> registers
    uint32_t qh[4][4];
    {
        const uint32_t* Q32 = (const uint32_t*)g_Qh;
        size_t base0 = ((size_t)bh * 2048 + qrow) * 32;
        size_t base1 = base0 + 8 * 32;
#pragma unroll
        for (int kt = 0; kt < 4; kt++) {
            qh[kt][0] = Q32[base0 + 8 * kt + tq];
            qh[kt][1] = Q32[base1 + 8 * kt + tq];
            qh[kt][2] = Q32[base0 + 8 * kt + 4 + tq];
            qh[kt][3] = Q32[base1 + 8 * kt + 4 + tq];
        }
    }

    LOAD_KB(0, 0);
    LOAD_KB(1, 1);

    float m_i[2] = {-1e30f, -1e30f};
    float l_i[2] = {0.f, 0.f};      // per-thread partial sums (quad-reduced at end)
    float o[8][4];
#pragma unroll
    for (int nt = 0; nt < 8; nt++)
#pragma unroll
        for (int e = 0; e < 4; e++) o[nt][e] = 0.f;

    const float* Bgb = Bg + (size_t)b * Nseq * Nseq;

    for (int kb = 0; kb < 32; kb++) {
        if (kb == 31) { CP_WAIT0(); } else { CP_WAIT1(); }
        __syncthreads();

        const uint32_t bufb = sb + 16384 + (kb & 1) * 32768;
        const uint32_t uKh = bufb;
        const uint32_t uKl = bufb + 8192;
        const uint32_t uVh = bufb + 16384;
        const uint32_t uVl = bufb + 24576;

        // S = Q K^T
        float s[8][4];
#pragma unroll
        for (int nt = 0; nt < 8; nt++)
#pragma unroll
            for (int e = 0; e < 4; e++) s[nt][e] = 0.f;

#pragma unroll
        for (int kt = 0; kt < 4; kt++) {
            uint32_t al[4];
            {
                int row = wm * 16 + 8 * (lt & 1) + lr;
                int wb = 8 * kt + 4 * (lt >> 1);
                ldsm_x4(al, sb + (uint32_t)QSW(row, wb) * 4);
            }
#pragma unroll
            for (int a = 0; a < 4; a++) {
                int row = 16 * a + 8 * (lt >> 1) + lr;
                int wb = 8 * kt + 4 * (lt & 1);
                uint32_t off = (uint32_t)QSW(row, wb) * 4;
                uint32_t kh4[4], kl4[4];
                ldsm_x4(kh4, uKh + off);
                ldsm_x4(kl4, uKl + off);
                uint32_t kh0[2] = {kh4[0], kh4[1]}, kh1[2] = {kh4[2], kh4[3]};
                uint32_t kl0[2] = {kl4[0], kl4[1]}, kl1[2] = {kl4[2], kl4[3]};
                mma_bf16(s[2 * a], qh[kt], kh0);
                mma_bf16(s[2 * a], qh[kt], kl0);
                mma_bf16(s[2 * a], al, kh0);
                mma_bf16(s[2 * a + 1], qh[kt], kh1);
                mma_bf16(s[2 * a + 1], qh[kt], kl1);
                mma_bf16(s[2 * a + 1], al, kh1);
            }
        }

        // base-2 scale + Gaussian bias: s2 = (qk*0.125 + lam*bg) * log2e
#pragma unroll
        for (int nt = 0; nt < 8; nt++) {
#pragma unroll
            for (int half = 0; half < 2; half++) {
                int row = qrow + half * 8;
                float2 bg = *(const float2*)(Bgb + (size_t)row * 2048 +
                                             kb * 64 + nt * 8 + tq * 2);
                s[nt][half * 2 + 0] = s[nt][half * 2 + 0] * scale2 + lam2 * bg.x;
                s[nt][half * 2 + 1] = s[nt][half * 2 + 1] * scale2 + lam2 * bg.y;
            }
        }

        // online softmax in base-2; l kept as per-thread partials
#pragma unroll
        for (int half = 0; half < 2; half++) {
            float mx = -1e30f;
#pragma unroll
            for (int nt = 0; nt < 8; nt++)
                mx = fmaxf(mx, fmaxf(s[nt][half * 2], s[nt][half * 2 + 1]));
            mx = fmaxf(mx, __shfl_xor_sync(0xffffffffu, mx, 1));
            mx = fmaxf(mx, __shfl_xor_sync(0xffffffffu, mx, 2));
            float mn = fmaxf(m_i[half], mx);
            float corr = exp2f(m_i[half] - mn);
            m_i[half] = mn;
            float rs = 0.f;
#pragma unroll
            for (int nt = 0; nt < 8; nt++) {
                s[nt][half * 2]     = exp2f(s[nt][half * 2] - mn);
                s[nt][half * 2 + 1] = exp2f(s[nt][half * 2 + 1] - mn);
                rs += s[nt][half * 2] + s[nt][half * 2 + 1];
            }
            l_i[half] = l_i[half] * corr + rs;   // per-thread partial (no shuffle)
#pragma unroll
            for (int nt = 0; nt < 8; nt++) {
                o[nt][half * 2]     *= corr;
                o[nt][half * 2 + 1] *= corr;
            }
        }

        // O += P V
#pragma unroll
        for (int kt = 0; kt < 4; kt++) {
            float h0, l0, h1, l1, h2, l2, h3, l3;
            uint32_t ph[4], pl[4];
            split1(s[2 * kt][0], h0, l0); split1(s[2 * kt][1], h1, l1);
            split1(s[2 * kt][2], h2, l2); split1(s[2 * kt][3], h3, l3);
            ph[0] = pack2(h0, h1); pl[0] = pack2(l0, l1);
            ph[1] = pack2(h2, h3); pl[1] = pack2(l2, l3);
            split1(s[2 * kt + 1][0], h0, l0); split1(s[2 * kt + 1][1], h1, l1);
            split1(s[2 * kt + 1][2], h2, l2); split1(s[2 * kt + 1][3], h3, l3);
            ph[2] = pack2(h0, h1); pl[2] = pack2(l0, l1);
            ph[3] = pack2(h2, h3); pl[3] = pack2(l2, l3);
#pragma unroll
            for (int a = 0; a < 4; a++) {
                int row = 16 * a + 8 * (lt >> 1) + lr;
                int wb = 8 * kt + 4 * (lt & 1);
                uint32_t off = (uint32_t)QSW(row, wb) * 4;
                uint32_t vh4[4], vl4[4];
                ldsm_x4(vh4, uVh + off);
                ldsm_x4(vl4, uVl + off);
                uint32_t vh0[2] = {vh4[0], vh4[1]}, vh1[2] = {vh4[2], vh4[3]};
                uint32_t vl0[2] = {vl4[0], vl4[1]}, vl1[2] = {vl4[2], vl4[3]};
                mma_bf16(o[2 * a], ph, vh0);
                mma_bf16(o[2 * a], ph, vl0);
                mma_bf16(o[2 * a], pl, vh0);
                mma_bf16(o[2 * a + 1], ph, vh1);
                mma_bf16(o[2 * a + 1], ph, vl1);
                mma_bf16(o[2 * a + 1], pl, vh1);
            }
        }

        __syncthreads();
        if (kb + 2 < 32) LOAD_KB(kb + 2, kb & 1);
    }

    // Epilogue: finish the deferred l reduction (quad), then normalize.
    float lsum0 = l_i[0], lsum1 = l_i[1];
    lsum0 += __shfl_xor_sync(0xffffffffu, lsum0, 1);
    lsum0 += __shfl_xor_sync(0xffffffffu, lsum0, 2);
    lsum1 += __shfl_xor_sync(0xffffffffu, lsum1, 1);
    lsum1 += __shfl_xor_sync(0xffffffffu, lsum1, 2);
    float inv0 = 1.0f / lsum0;
    float inv1 = 1.0f / lsum1;
#pragma unroll
    for (int nt = 0; nt < 8; nt++) {
#pragma unroll
        for (int half = 0; half < 2; half++) {
            float inv = half ? inv1 : inv0;
            int row = qrow + half * 8;
            float v0 = o[nt][half * 2 + 0] * inv;
            float v1 = o[nt][half * 2 + 1] * inv;
            float h0, l0, h1, l1;
            split1(v0, h0, l0);
            split1(v1, h1, l1);
            size_t ui = ((size_t)(b * 2048) + row) * 512 + h * 32 + nt * 4 + tq;
            ((uint32_t*)g_oh)[ui] = pack2(h0, h1);
            ((uint32_t*)g_ol)[ui] = pack2(l0, l1);
        }
    }
}

// ---------------------------------------------------------------------------
extern "C" void kernel_launch(void* const* d_in, const int* in_sizes, int n_in,
                              void* d_out, int out_size)
{
    const float* x   = (const float*)d_in[0];
    const float* Bg  = (const float*)d_in[1];
    const float* Wq  = (const float*)d_in[2];
    const float* bq  = (const float*)d_in[3];
    const float* Wk  = (const float*)d_in[4];
    const float* bk  = (const float*)d_in[5];
    const float* Wv  = (const float*)d_in[6];
    const float* bv  = (const float*)d_in[7];
    const float* Wo  = (const float*)d_in[8];
    const float* bo  = (const float*)d_in[9];
    const float* lam = (const float*)d_in[10];
    float* out = (float*)d_out;

    cudaFuncSetAttribute(attn_mma, cudaFuncAttributeMaxDynamicSharedMemorySize, ATT_SMEM);
    cudaFuncSetAttribute(mma_qkv, cudaFuncAttributeMaxDynamicSharedMemorySize, GEMM_SMEM);
    cudaFuncSetAttribute(mma_out, cudaFuncAttributeMaxDynamicSharedMemorySize, GEMM_SMEM);

    conv_split_x<<<4096, 256>>>((const float4*)x);
    conv_w<<<dim3(32, 32, 4), dim3(32, 8)>>>(Wq, Wk, Wv, Wo);

    mma_qkv<<<dim3(8, 32, 3), 256, GEMM_SMEM>>>(bq, bk, bv);
    transpose_v<<<dim3(64, 2, 32), dim3(32, 8)>>>();

    attn_mma<<<dim3(16, 16, 2), 256, ATT_SMEM>>>(Bg, lam);

    mma_out<<<dim3(8, 32, 1), 256, GEMM_SMEM>>>(bo, out);
}

// round 13
// speedup vs baseline: 1.0656x; 1.0280x over previous
#include <cuda_runtime.h>
#include <cuda_bf16.h>
#include <cstdint>
#include <math.h>

// Problem constants
#define Bdim 2
#define Nseq 2048
#define Dmod 1024
#define Hn   16
#define HD   64

// ---------------------------------------------------------------------------
// Scratch (alloc-free rule: __device__ globals)
// ---------------------------------------------------------------------------
#define QKV_ELEMS ((size_t)Bdim * Hn * Nseq * HD)
__device__ __nv_bfloat16 g_Qh[QKV_ELEMS], g_Ql[QKV_ELEMS];   // [b][h][n][d]
__device__ __nv_bfloat16 g_Kh[QKV_ELEMS], g_Kl[QKV_ELEMS];
__device__ __nv_bfloat16 g_Vh[QKV_ELEMS], g_Vl[QKV_ELEMS];   // [b][h][n][d]

__device__ __nv_bfloat16 g_xh[(size_t)4096 * 1024];
__device__ __nv_bfloat16 g_xl[(size_t)4096 * 1024];
__device__ __nv_bfloat16 g_oh[(size_t)4096 * 1024];          // attn out [b][n][1024]
__device__ __nv_bfloat16 g_ol[(size_t)4096 * 1024];
__device__ __nv_bfloat16 g_wth[4][(size_t)1024 * 1024];      // W^T [n][k]
__device__ __nv_bfloat16 g_wtl[4][(size_t)1024 * 1024];

// ---------------------------------------------------------------------------
// PTX helpers
// ---------------------------------------------------------------------------
__device__ __forceinline__ void mma_bf16(float (&d)[4],
                                         const uint32_t (&a)[4],
                                         const uint32_t (&b)[2])
{
    asm volatile(
        "mma.sync.aligned.m16n8k16.row.col.f32.bf16.bf16.f32 "
        "{%0,%1,%2,%3}, {%4,%5,%6,%7}, {%8,%9}, {%0,%1,%2,%3};"
        : "+f"(d[0]), "+f"(d[1]), "+f"(d[2]), "+f"(d[3])
        : "r"(a[0]), "r"(a[1]), "r"(a[2]), "r"(a[3]),
          "r"(b[0]), "r"(b[1]));
}

__device__ __forceinline__ void ldsm_x4(uint32_t (&r)[4], uint32_t addr)
{
    asm volatile("ldmatrix.sync.aligned.m8n8.x4.shared.b16 {%0,%1,%2,%3}, [%4];"
                 : "=r"(r[0]), "=r"(r[1]), "=r"(r[2]), "=r"(r[3]) : "r"(addr));
}

__device__ __forceinline__ void ldsm_x4_trans(uint32_t (&r)[4], uint32_t addr)
{
    asm volatile("ldmatrix.sync.aligned.m8n8.x4.trans.shared.b16 {%0,%1,%2,%3}, [%4];"
                 : "=r"(r[0]), "=r"(r[1]), "=r"(r[2]), "=r"(r[3]) : "r"(addr));
}

__device__ __forceinline__ uint32_t smem_to_u32(const void* p) {
    uint32_t a;
    asm("{ .reg .u64 t; cvta.to.shared.u64 t, %1; cvt.u32.u64 %0, t; }"
        : "=r"(a) : "l"(p));
    return a;
}

#define CP_ASYNC16(saddr, gptr) \
    asm volatile("cp.async.cg.shared.global [%0], [%1], 16;" \
                 :: "r"(saddr), "l"(gptr) : "memory")
#define CP_COMMIT() asm volatile("cp.async.commit_group;" ::: "memory")
#define CP_WAIT1()  asm volatile("cp.async.wait_group 1;" ::: "memory")
#define CP_WAIT0()  asm volatile("cp.async.wait_group 0;" ::: "memory")

__device__ __forceinline__ uint32_t pack2(float a, float b)
{
    return (uint32_t)__bfloat16_as_ushort(__float2bfloat16_rn(a)) |
           ((uint32_t)__bfloat16_as_ushort(__float2bfloat16_rn(b)) << 16);
}

__device__ __forceinline__ void split1(float v, float& hf, float& lf)
{
    __nv_bfloat16 h = __float2bfloat16_rn(v);
    hf = __bfloat162float(h);
    lf = v - hf;
}

// ---------------------------------------------------------------------------
// Merged conversion kernel:
//  blocks [0, 4096)        : x fp32 -> bf16 hi/lo split
//  blocks [4096, 8192)     : W[k][n] -> W^T[n][k] bf16 hi/lo (4 matrices)
// ---------------------------------------------------------------------------
__global__ void conv_all(const float4* __restrict__ x,
                         const float* __restrict__ Wq, const float* __restrict__ Wk,
                         const float* __restrict__ Wv, const float* __restrict__ Wo)
{
    __shared__ float t[32][33];
    int bz = blockIdx.x;
    int tid = threadIdx.x;

    if (bz < 4096) {
        int i = bz * 256 + tid;
        float4 v = x[i];
        __nv_bfloat16 h0 = __float2bfloat16_rn(v.x);
        __nv_bfloat16 h1 = __float2bfloat16_rn(v.y);
        __nv_bfloat16 h2 = __float2bfloat16_rn(v.z);
        __nv_bfloat16 h3 = __float2bfloat16_rn(v.w);
        ushort4 H = {__bfloat16_as_ushort(h0), __bfloat16_as_ushort(h1),
                     __bfloat16_as_ushort(h2), __bfloat16_as_ushort(h3)};
        ushort4 L = {__bfloat16_as_ushort(__float2bfloat16_rn(v.x - __bfloat162float(h0))),
                     __bfloat16_as_ushort(__float2bfloat16_rn(v.y - __bfloat162float(h1))),
                     __bfloat16_as_ushort(__float2bfloat16_rn(v.z - __bfloat162float(h2))),
                     __bfloat16_as_ushort(__float2bfloat16_rn(v.w - __bfloat162float(h3)))};
        ((ushort4*)g_xh)[i] = H;
        ((ushort4*)g_xl)[i] = L;
    } else {
        int r = bz - 4096;
        int z = r >> 10;
        int rr = r & 1023;
        const float* W = (z == 0) ? Wq : (z == 1) ? Wk : (z == 2) ? Wv : Wo;
        int n0 = (rr & 31) * 32;
        int k0 = (rr >> 5) * 32;
        int tx = tid & 31;
        int ty = tid >> 5;      // 0..7
#pragma unroll
        for (int j = 0; j < 32; j += 8)
            t[ty + j][tx] = W[(size_t)(k0 + ty + j) * 1024 + n0 + tx];
        __syncthreads();
#pragma unroll
        for (int j = 0; j < 32; j += 8) {
            float v = t[tx][ty + j];
            __nv_bfloat16 h = __float2bfloat16_rn(v);
            __nv_bfloat16 l = __float2bfloat16_rn(v - __bfloat162float(h));
            size_t idx = (size_t)(n0 + ty + j) * 1024 + k0 + tx;
            g_wth[z][idx] = h;
            g_wtl[z][idx] = l;
        }
    }
}

// ---------------------------------------------------------------------------
// HMMA bf16x3 GEMM with ldmatrix fragments + cp.async double buffering (R7).
// C[4096,1024] = A @ B^T + bias (B stored [n][k]).
// ---------------------------------------------------------------------------
#define TSTRIDE 20
#define GT 10240
#define GBUF (4 * GT)
#define GEMM_SMEM (2 * GBUF)

template <bool HEAD>
__device__ __forceinline__ void mma_gemm_body(const __nv_bfloat16* __restrict__ Ahi,
                                              const __nv_bfloat16* __restrict__ Alo,
                                              const __nv_bfloat16* __restrict__ Bhi,
                                              const __nv_bfloat16* __restrict__ Blo,
                                              const float* __restrict__ bias,
                                              float* __restrict__ out,
                                              __nv_bfloat16* __restrict__ outH,
                                              __nv_bfloat16* __restrict__ outL)
{
    extern __shared__ char gsm[];
    const uint32_t gb = smem_to_u32(gsm);

    const int tid = threadIdx.x;
    const int wid = tid >> 5;
    const int lid = tid & 31;
    const int wm  = wid & 3;
    const int wn  = wid >> 2;
    const int gq  = lid >> 2;
    const int tq  = lid & 3;
    const int lt  = lid >> 3;
    const int lr  = lid & 7;
    const int m0 = blockIdx.y * 128;
    const int n0 = blockIdx.x * 128;

    const int u0row = (tid * 2) >> 2;
    const int u0c4  = (tid * 2) & 3;
    const int u1row = (tid * 2 + 1) >> 2;
    const int u1c4  = (tid * 2 + 1) & 3;

#define G_LOAD(kt, bi) do { \
        uint32_t buf = gb + (bi) * GBUF; \
        { \
            uint32_t so = (uint32_t)(u0row * TSTRIDE + u0c4 * 4) * 4; \
            const char* pa = (const char*)(Ahi + (size_t)(m0 + u0row) * 1024 + (kt)); \
            const char* pal = (const char*)(Alo + (size_t)(m0 + u0row) * 1024 + (kt)); \
            const char* pb = (const char*)(Bhi + (size_t)(n0 + u0row) * 1024 + (kt)); \
            const char* pbl = (const char*)(Blo + (size_t)(n0 + u0row) * 1024 + (kt)); \
            CP_ASYNC16(buf + so,          pa  + u0c4 * 16); \
            CP_ASYNC16(buf + GT + so,     pal + u0c4 * 16); \
            CP_ASYNC16(buf + 2 * GT + so, pb  + u0c4 * 16); \
            CP_ASYNC16(buf + 3 * GT + so, pbl + u0c4 * 16); \
        } \
        { \
            uint32_t so = (uint32_t)(u1row * TSTRIDE + u1c4 * 4) * 4; \
            const char* pa = (const char*)(Ahi + (size_t)(m0 + u1row) * 1024 + (kt)); \
            const char* pal = (const char*)(Alo + (size_t)(m0 + u1row) * 1024 + (kt)); \
            const char* pb = (const char*)(Bhi + (size_t)(n0 + u1row) * 1024 + (kt)); \
            const char* pbl = (const char*)(Blo + (size_t)(n0 + u1row) * 1024 + (kt)); \
            CP_ASYNC16(buf + so,          pa  + u1c4 * 16); \
            CP_ASYNC16(buf + GT + so,     pal + u1c4 * 16); \
            CP_ASYNC16(buf + 2 * GT + so, pb  + u1c4 * 16); \
            CP_ASYNC16(buf + 3 * GT + so, pbl + u1c4 * 16); \
        } \
        CP_COMMIT(); \
    } while (0)

    float acc[2][8][4];
#pragma unroll
    for (int mt = 0; mt < 2; mt++)
#pragma unroll
        for (int nt = 0; nt < 8; nt++)
#pragma unroll
            for (int e = 0; e < 4; e++) acc[mt][nt][e] = 0.f;

    G_LOAD(0, 0);
    G_LOAD(32, 1);

    for (int it = 0; it < 32; it++) {
        if (it == 31) { CP_WAIT0(); } else { CP_WAIT1(); }
        __syncthreads();

        const uint32_t buf = gb + (it & 1) * GBUF;
        const uint32_t uAh = buf;
        const uint32_t uAl = buf + GT;
        const uint32_t uBh = buf + 2 * GT;
        const uint32_t uBl = buf + 3 * GT;

#pragma unroll
        for (int ks = 0; ks < 2; ks++) {
            const int c0 = ks * 8;
            uint32_t bh[8][2], bl[8][2];
#pragma unroll
            for (int a = 0; a < 4; a++) {
                int row = wn * 64 + 16 * a + 8 * (lt >> 1) + lr;
                int col = c0 + 4 * (lt & 1);
                uint32_t off = (uint32_t)(row * TSTRIDE + col) * 4;
                uint32_t f[4];
                ldsm_x4(f, uBh + off);
                bh[2 * a][0] = f[0]; bh[2 * a][1] = f[1];
                bh[2 * a + 1][0] = f[2]; bh[2 * a + 1][1] = f[3];
                ldsm_x4(f, uBl + off);
                bl[2 * a][0] = f[0]; bl[2 * a][1] = f[1];
                bl[2 * a + 1][0] = f[2]; bl[2 * a + 1][1] = f[3];
            }
#pragma unroll
            for (int mt = 0; mt < 2; mt++) {
                int row = wm * 32 + 16 * mt + 8 * (lt & 1) + lr;
                int col = c0 + 4 * (lt >> 1);
                uint32_t off = (uint32_t)(row * TSTRIDE + col) * 4;
                uint32_t ah[4], al[4];
                ldsm_x4(ah, uAh + off);
                ldsm_x4(al, uAl + off);
#pragma unroll
                for (int nt = 0; nt < 8; nt++) {
                    mma_bf16(acc[mt][nt], ah, bh[nt]);
                    mma_bf16(acc[mt][nt], ah, bl[nt]);
                    mma_bf16(acc[mt][nt], al, bh[nt]);
                }
            }
        }
        __syncthreads();
        if (it + 2 < 32) G_LOAD((it + 2) * 32, it & 1);
    }

#pragma unroll
    for (int mt = 0; mt < 2; mt++) {
#pragma unroll
        for (int nt = 0; nt < 8; nt++) {
            int R = m0 + wm * 32 + mt * 16 + gq;
            int C = n0 + wn * 64 + nt * 8 + tq * 2;
            float b0 = bias[C], b1 = bias[C + 1];
#pragma unroll
            for (int half = 0; half < 2; half++) {
                int r = R + half * 8;
                float v0 = acc[mt][nt][half * 2 + 0] + b0;
                float v1 = acc[mt][nt][half * 2 + 1] + b1;
                if (HEAD) {
                    int b = r >> 11;
                    int n = r & 2047;
                    int hh = C >> 6;
                    int d = C & 63;
                    float h0, l0, h1, l1;
                    split1(v0, h0, l0);
                    split1(v1, h1, l1);
                    size_t ui = (((size_t)(b * Hn + hh)) * 2048 + n) * 32 + (d >> 1);
                    ((uint32_t*)outH)[ui] = pack2(h0, h1);
                    ((uint32_t*)outL)[ui] = pack2(l0, l1);
                } else {
                    *(float2*)(out + (size_t)r * 1024 + C) = make_float2(v0, v1);
                }
            }
        }
    }
#undef G_LOAD
}

__global__ void __launch_bounds__(256, 2)
mma_qkv(const float* __restrict__ bq, const float* __restrict__ bk,
        const float* __restrict__ bv)
{
    int z = blockIdx.z;
    const float* bias = (z == 0) ? bq : (z == 1) ? bk : bv;
    __nv_bfloat16* oh = (z == 0) ? g_Qh : (z == 1) ? g_Kh : g_Vh;
    __nv_bfloat16* ol = (z == 0) ? g_Ql : (z == 1) ? g_Kl : g_Vl;
    mma_gemm_body<true>(g_xh, g_xl, g_wth[z], g_wtl[z], bias, nullptr, oh, ol);
}

__global__ void __launch_bounds__(256, 2)
mma_out(const float* __restrict__ bo, float* __restrict__ out)
{
    mma_gemm_body<false>(g_oh, g_ol, g_wth[3], g_wtl[3], bo, out, nullptr, nullptr);
}

// ---------------------------------------------------------------------------
// HMMA flash attention v9 (R12 base): base-2 softmax, deferred l-reduction,
// 2-stage K/V cp.async ring. NEW: V consumed in natural [n][d] layout via
// ldmatrix.trans (transpose_v kernel deleted).
// Smem: 16KB Q-lo + 2 x 32KB K/V = 80KB; 2 CTAs/SM.
// ---------------------------------------------------------------------------
#define QSW(r, w) (((r) * 32) + ((w) ^ (((r) & 7) << 2)))
#define ATT_SMEM (16384 + 2 * 32768)
#define LOG2E 1.4426950408889634f

__global__ void __launch_bounds__(256, 2)
attn_mma(const float* __restrict__ Bg, const float* __restrict__ lam_p)
{
    extern __shared__ char smem[];
    const uint32_t sb = smem_to_u32(smem);

    const int tid = threadIdx.x;
    const int wm  = tid >> 5;
    const int lid = tid & 31;
    const int gq  = lid >> 2;
    const int tq  = lid & 3;
    const int lt  = lid >> 3;
    const int lr  = lid & 7;
    const int qb = blockIdx.x;
    const int h  = blockIdx.y;
    const int b  = blockIdx.z;
    const int bh = b * Hn + h;
    const int q0 = qb * 128;

    const float lam2   = __ldg(lam_p) * LOG2E;   // lam * log2(e)
    const float scale2 = 0.125f * LOG2E;         // (1/sqrt(64)) * log2(e)

    const int r0 = wm * 16 + gq;
    const int qrow = q0 + r0;

    const int ldrow = tid >> 2;
    const int ldq   = tid & 3;
    const uint32_t lw0 = (uint32_t)((4 * ldq) ^ ((ldrow & 7) << 2)) * 4;
    const uint32_t lw1 = (uint32_t)((4 * ldq + 16) ^ ((ldrow & 7) << 2)) * 4;
    const uint32_t lrow128 = (uint32_t)ldrow * 128;

// K and V both loaded in [n(j)][d] layout, rows = 64 j, 128B per row.
#define LOAD_KB(kb, bi) do { \
        uint32_t bufb = sb + 16384 + (bi) * 32768; \
        const char* pKh = (const char*)(g_Kh + ((size_t)bh * 2048 + (kb) * 64 + ldrow) * 64); \
        const char* pKl = (const char*)(g_Kl + ((size_t)bh * 2048 + (kb) * 64 + ldrow) * 64); \
        const char* pVh = (const char*)(g_Vh + ((size_t)bh * 2048 + (kb) * 64 + ldrow) * 64); \
        const char* pVl = (const char*)(g_Vl + ((size_t)bh * 2048 + (kb) * 64 + ldrow) * 64); \
        CP_ASYNC16(bufb + lrow128 + lw0, pKh + ldq * 16); \
        CP_ASYNC16(bufb + lrow128 + lw1, pKh + 64 + ldq * 16); \
        CP_ASYNC16(bufb + 8192 + lrow128 + lw0, pKl + ldq * 16); \
        CP_ASYNC16(bufb + 8192 + lrow128 + lw1, pKl + 64 + ldq * 16); \
        CP_ASYNC16(bufb + 16384 + lrow128 + lw0, pVh + ldq * 16); \
        CP_ASYNC16(bufb + 16384 + lrow128 + lw1, pVh + 64 + ldq * 16); \
        CP_ASYNC16(bufb + 24576 + lrow128 + lw0, pVl + ldq * 16); \
        CP_ASYNC16(bufb + 24576 + lrow128 + lw1, pVl + 64 + ldq * 16); \
        CP_COMMIT(); \
    } while (0)

    // Q-lo tile -> smem
    {
        const __nv_bfloat16* Qlg = g_Ql + ((size_t)bh * 2048 + q0) * 64;
#pragma unroll
        for (int i = 0; i < 4; i++) {
            int u = tid + i * 256;
            int row = u >> 3;
            int c4 = u & 7;
            int w = (4 * c4) ^ ((row & 7) << 2);
            *(uint4*)(smem + (row * 32 + w) * 4) = ((const uint4*)(Qlg + (size_t)row * 64))[c4];
        }
    }

    // Q-hi fragments -> registers
    uint32_t qh[4][4];
    {
        const uint32_t* Q32 = (const uint32_t*)g_Qh;
        size_t base0 = ((size_t)bh * 2048 + qrow) * 32;
        size_t base1 = base0 + 8 * 32;
#pragma unroll
        for (int kt = 0; kt < 4; kt++) {
            qh[kt][0] = Q32[base0 + 8 * kt + tq];
            qh[kt][1] = Q32[base1 + 8 * kt + tq];
            qh[kt][2] = Q32[base0 + 8 * kt + 4 + tq];
            qh[kt][3] = Q32[base1 + 8 * kt + 4 + tq];
        }
    }

    LOAD_KB(0, 0);
    LOAD_KB(1, 1);

    float m_i[2] = {-1e30f, -1e30f};
    float l_i[2] = {0.f, 0.f};      // per-thread partials, quad-reduced at end
    float o[8][4];
#pragma unroll
    for (int nt = 0; nt < 8; nt++)
#pragma unroll
        for (int e = 0; e < 4; e++) o[nt][e] = 0.f;

    const float* Bgb = Bg + (size_t)b * Nseq * Nseq;

    for (int kb = 0; kb < 32; kb++) {
        if (kb == 31) { CP_WAIT0(); } else { CP_WAIT1(); }
        __syncthreads();

        const uint32_t bufb = sb + 16384 + (kb & 1) * 32768;
        const uint32_t uKh = bufb;
        const uint32_t uKl = bufb + 8192;
        const uint32_t uVh = bufb + 16384;
        const uint32_t uVl = bufb + 24576;

        // S = Q K^T
        float s[8][4];
#pragma unroll
        for (int nt = 0; nt < 8; nt++)
#pragma unroll
            for (int e = 0; e < 4; e++) s[nt][e] = 0.f;

#pragma unroll
        for (int kt = 0; kt < 4; kt++) {
            uint32_t al[4];
            {
                int row = wm * 16 + 8 * (lt & 1) + lr;
                int wb = 8 * kt + 4 * (lt >> 1);
                ldsm_x4(al, sb + (uint32_t)QSW(row, wb) * 4);
            }
#pragma unroll
            for (int a = 0; a < 4; a++) {
                int row = 16 * a + 8 * (lt >> 1) + lr;
                int wb = 8 * kt + 4 * (lt & 1);
                uint32_t off = (uint32_t)QSW(row, wb) * 4;
                uint32_t kh4[4], kl4[4];
                ldsm_x4(kh4, uKh + off);
                ldsm_x4(kl4, uKl + off);
                uint32_t kh0[2] = {kh4[0], kh4[1]}, kh1[2] = {kh4[2], kh4[3]};
                uint32_t kl0[2] = {kl4[0], kl4[1]}, kl1[2] = {kl4[2], kl4[3]};
                mma_bf16(s[2 * a], qh[kt], kh0);
                mma_bf16(s[2 * a], qh[kt], kl0);
                mma_bf16(s[2 * a], al, kh0);
                mma_bf16(s[2 * a + 1], qh[kt], kh1);
                mma_bf16(s[2 * a + 1], qh[kt], kl1);
                mma_bf16(s[2 * a + 1], al, kh1);
            }
        }

        // base-2 scale + Gaussian bias
#pragma unroll
        for (int nt = 0; nt < 8; nt++) {
#pragma unroll
            for (int half = 0; half < 2; half++) {
                int row = qrow + half * 8;
                float2 bg = *(const float2*)(Bgb + (size_t)row * 2048 +
                                             kb * 64 + nt * 8 + tq * 2);
                s[nt][half * 2 + 0] = s[nt][half * 2 + 0] * scale2 + lam2 * bg.x;
                s[nt][half * 2 + 1] = s[nt][half * 2 + 1] * scale2 + lam2 * bg.y;
            }
        }

        // online softmax in base-2; l kept as per-thread partials
#pragma unroll
        for (int half = 0; half < 2; half++) {
            float mx = -1e30f;
#pragma unroll
            for (int nt = 0; nt < 8; nt++)
                mx = fmaxf(mx, fmaxf(s[nt][half * 2], s[nt][half * 2 + 1]));
            mx = fmaxf(mx, __shfl_xor_sync(0xffffffffu, mx, 1));
            mx = fmaxf(mx, __shfl_xor_sync(0xffffffffu, mx, 2));
            float mn = fmaxf(m_i[half], mx);
            float corr = exp2f(m_i[half] - mn);
            m_i[half] = mn;
            float rs = 0.f;
#pragma unroll
            for (int nt = 0; nt < 8; nt++) {
                s[nt][half * 2]     = exp2f(s[nt][half * 2] - mn);
                s[nt][half * 2 + 1] = exp2f(s[nt][half * 2 + 1] - mn);
                rs += s[nt][half * 2] + s[nt][half * 2 + 1];
            }
            l_i[half] = l_i[half] * corr + rs;
#pragma unroll
            for (int nt = 0; nt < 8; nt++) {
                o[nt][half * 2]     *= corr;
                o[nt][half * 2 + 1] *= corr;
            }
        }

        // O += P V   (V fragments via ldmatrix.trans from [j][d] tiles)
#pragma unroll
        for (int kt = 0; kt < 4; kt++) {
            float h0, l0, h1, l1, h2, l2, h3, l3;
            uint32_t ph[4], pl[4];
            split1(s[2 * kt][0], h0, l0); split1(s[2 * kt][1], h1, l1);
            split1(s[2 * kt][2], h2, l2); split1(s[2 * kt][3], h3, l3);
            ph[0] = pack2(h0, h1); pl[0] = pack2(l0, l1);
            ph[1] = pack2(h2, h3); pl[1] = pack2(l2, l3);
            split1(s[2 * kt + 1][0], h0, l0); split1(s[2 * kt + 1][1], h1, l1);
            split1(s[2 * kt + 1][2], h2, l2); split1(s[2 * kt + 1][3], h3, l3);
            ph[2] = pack2(h0, h1); pl[2] = pack2(l0, l1);
            ph[3] = pack2(h2, h3); pl[3] = pack2(l2, l3);
#pragma unroll
            for (int a = 0; a < 4; a++) {
                // source tile (j-rows, d-chunk): rows j = 16kt + 8*(lt&1) + lr,
                // d word = 8a + 4*(lt>>1). trans -> Vt fragment, tile order
                // T0=(d0,j0) T1=(d0,j1) T2=(d1,j0) T3=(d1,j1).
                int rowj = 16 * kt + 8 * (lt & 1) + lr;
                int wd   = 8 * a + 4 * (lt >> 1);
                uint32_t off = (uint32_t)QSW(rowj, wd) * 4;
                uint32_t vh4[4], vl4[4];
                ldsm_x4_trans(vh4, uVh + off);
                ldsm_x4_trans(vl4, uVl + off);
                uint32_t vh0[2] = {vh4[0], vh4[1]}, vh1[2] = {vh4[2], vh4[3]};
                uint32_t vl0[2] = {vl4[0], vl4[1]}, vl1[2] = {vl4[2], vl4[3]};
                mma_bf16(o[2 * a], ph, vh0);
                mma_bf16(o[2 * a], ph, vl0);
                mma_bf16(o[2 * a], pl, vh0);
                mma_bf16(o[2 * a + 1], ph, vh1);
                mma_bf16(o[2 * a + 1], ph, vl1);
                mma_bf16(o[2 * a + 1], pl, vh1);
            }
        }

        __syncthreads();
        if (kb + 2 < 32) LOAD_KB(kb + 2, kb & 1);
    }

    // Epilogue: finish deferred l reduction (quad), then normalize.
    float lsum0 = l_i[0], lsum1 = l_i[1];
    lsum0 += __shfl_xor_sync(0xffffffffu, lsum0, 1);
    lsum0 += __shfl_xor_sync(0xffffffffu, lsum0, 2);
    lsum1 += __shfl_xor_sync(0xffffffffu, lsum1, 1);
    lsum1 += __shfl_xor_sync(0xffffffffu, lsum1, 2);
    float inv0 = 1.0f / lsum0;
    float inv1 = 1.0f / lsum1;
#pragma unroll
    for (int nt = 0; nt < 8; nt++) {
#pragma unroll
        for (int half = 0; half < 2; half++) {
            float inv = half ? inv1 : inv0;
            int row = qrow + half * 8;
            float v0 = o[nt][half * 2 + 0] * inv;
            float v1 = o[nt][half * 2 + 1] * inv;
            float h0, l0, h1, l1;
            split1(v0, h0, l0);
            split1(v1, h1, l1);
            size_t ui = ((size_t)(b * 2048) + row) * 512 + h * 32 + nt * 4 + tq;
            ((uint32_t*)g_oh)[ui] = pack2(h0, h1);
            ((uint32_t*)g_ol)[ui] = pack2(l0, l1);
        }
    }
}

// ---------------------------------------------------------------------------
extern "C" void kernel_launch(void* const* d_in, const int* in_sizes, int n_in,
                              void* d_out, int out_size)
{
    const float* x   = (const float*)d_in[0];
    const float* Bg  = (const float*)d_in[1];
    const float* Wq  = (const float*)d_in[2];
    const float* bq  = (const float*)d_in[3];
    const float* Wk  = (const float*)d_in[4];
    const float* bk  = (const float*)d_in[5];
    const float* Wv  = (const float*)d_in[6];
    const float* bv  = (const float*)d_in[7];
    const float* Wo  = (const float*)d_in[8];
    const float* bo  = (const float*)d_in[9];
    const float* lam = (const float*)d_in[10];
    float* out = (float*)d_out;

    cudaFuncSetAttribute(attn_mma, cudaFuncAttributeMaxDynamicSharedMemorySize, ATT_SMEM);
    cudaFuncSetAttribute(mma_qkv, cudaFuncAttributeMaxDynamicSharedMemorySize, GEMM_SMEM);
    cudaFuncSetAttribute(mma_out, cudaFuncAttributeMaxDynamicSharedMemorySize, GEMM_SMEM);

    conv_all<<<8192, 256>>>((const float4*)x, Wq, Wk, Wv, Wo);

    mma_qkv<<<dim3(8, 32, 3), 256, GEMM_SMEM>>>(bq, bk, bv);

    attn_mma<<<dim3(16, 16, 2), 256, ATT_SMEM>>>(Bg, lam);

    mma_out<<<dim3(8, 32, 1), 256, GEMM_SMEM>>>(bo, out);
}